// round 1
// baseline (speedup 1.0000x reference)
#include <cuda_runtime.h>

// Problem constants
#define Bn 64
#define On 4000
#define Mn 128
#define Dn 64
#define SPLIT 20
#define CHUNK 200   // On / SPLIT
#define TO 40       // opes per smem tile
#define TILES 5     // CHUNK / TO

// ---------------- device scratch (allocation-free rule: __device__ globals) ----
__device__ float g_vope[Dn];                                  // W_ope^T @ alpha_ope
__device__ float g_amac[Bn * Mn];                             // a_mac
__device__ float g_hmac[(size_t)Bn * Mn * Dn];                // h_mac
__device__ float g_part[(size_t)Bn * SPLIT * Mn * Dn];        // split-K partial acc (41.9MB)
__device__ float g_partZ[Bn * SPLIT * Mn];                    // split-K partial Z

// ---------------- f32x2 helpers ------------------------------------------------
__device__ __forceinline__ unsigned long long pk2(float a, float b) {
    unsigned long long r;
    asm("mov.b64 %0, {%1,%2};" : "=l"(r) : "f"(a), "f"(b));
    return r;
}
__device__ __forceinline__ void upk2(unsigned long long v, float& a, float& b) {
    asm("mov.b64 {%0,%1}, %2;" : "=f"(a), "=f"(b) : "l"(v));
}
__device__ __forceinline__ void ffma2(unsigned long long& d, unsigned long long a,
                                      unsigned long long b) {
    asm("fma.rn.f32x2 %0, %1, %2, %0;" : "+l"(d) : "l"(a), "l"(b));
}

// ---------------- kernel 1: v = W_ope^T @ alpha_ope ---------------------------
__global__ void vope_kernel(const float* __restrict__ W_ope,
                            const float* __restrict__ alpha_ope) {
    int d = threadIdx.x;   // 64 threads
    float s = 0.f;
#pragma unroll 8
    for (int k = 0; k < Dn; ++k) s += alpha_ope[k] * W_ope[k * Dn + d];
    g_vope[d] = s;
}

// ---------------- kernel 2: h_mac + a_mac -------------------------------------
// grid = Bn*Mn blocks of 64 threads; block = one (b,m) row; thread = one k.
__global__ void hmac_kernel(const float* __restrict__ feat_mac,
                            const float* __restrict__ W_mac,
                            const float* __restrict__ alpha_mac) {
    int bm = blockIdx.x;          // b*128 + m
    int k = threadIdx.x;          // 0..63
    const float4* fr = (const float4*)(feat_mac + (size_t)bm * Dn);
    const float4* wr = (const float4*)(W_mac + (size_t)k * Dn);
    float acc = 0.f;
#pragma unroll
    for (int j = 0; j < 16; ++j) {
        float4 f = __ldg(fr + j);
        float4 w = __ldg(wr + j);
        acc += f.x * w.x + f.y * w.y + f.z * w.z + f.w * w.w;
    }
    g_hmac[(size_t)bm * Dn + k] = acc;
    float pa = acc * __ldg(alpha_mac + k);
#pragma unroll
    for (int s = 16; s > 0; s >>= 1) pa += __shfl_xor_sync(0xFFFFFFFFu, pa, s);
    __shared__ float sred[2];
    if ((k & 31) == 0) sred[k >> 5] = pa;
    __syncthreads();
    if (k == 0) g_amac[bm] = sred[0] + sred[1];
}

// ---------------- kernel 3: main attention reduction --------------------------
// grid (SPLIT, Bn), 128 threads. Per-thread register tile: 8 m x 8 d (f32x2 x32).
// Thread layout: mg = t>>3 (m = 8*mg..8*mg+7), dg = t&7
//   d-set per thread = {4*dg..4*dg+3} U {32+4*dg..32+4*dg+3}  (bank-conflict-free)
__global__ void __launch_bounds__(128, 4)
main_kernel(const float* __restrict__ proc, const float* __restrict__ feat) {
    const int b = blockIdx.y, sp = blockIdx.x;
    const int t = threadIdx.x, lane = t & 31, warp = t >> 5;
    const int mg = t >> 3, dg = t & 7;

    __shared__ float s_feat[TO * 64];     // 10.25 KB
    __shared__ float s_w[TO * 128];       // 20.5 KB
    __shared__ float s_aope[TO];
    __shared__ float s_amac[128];

    if (t < 128) s_amac[t] = g_amac[b * Mn + t];
    float4 v4 = *(const float4*)(g_vope + ((4 * t) & 63));
    __syncthreads();
    float4 am4 = *(const float4*)(s_amac + lane * 4);   // a_mac for m = 4*lane..+3

    const float* procB = proc + (size_t)b * On * Mn;
    const float* featB = feat + (size_t)b * On * 64;

    unsigned long long acc[32];
#pragma unroll
    for (int i = 0; i < 32; ++i) acc[i] = 0ull;
    float zacc = 0.f;

    const int o0 = sp * CHUNK;
    for (int tile = 0; tile < TILES; ++tile) {
        const int ob = o0 + tile * TO;

        // ---- phase a: load feat tile (2560 floats) + compute a_ope per o ----
        float4 f4[5];
        float pa[5];
        const float* fptr = featB + (size_t)ob * 64;
#pragma unroll
        for (int j = 0; j < 5; ++j) {
            // lin = 4t + 512j : o = (t>>4)+8j, d = (4t)&63
            f4[j] = __ldg((const float4*)(fptr + 4 * t + 512 * j));
            pa[j] = f4[j].x * v4.x + f4[j].y * v4.y + f4[j].z * v4.z + f4[j].w * v4.w;
        }
#pragma unroll
        for (int s = 1; s < 16; s <<= 1) {
#pragma unroll
            for (int j = 0; j < 5; ++j) pa[j] += __shfl_xor_sync(0xFFFFFFFFu, pa[j], s);
        }
        if ((t & 15) == 0) {
#pragma unroll
            for (int j = 0; j < 5; ++j) s_aope[(t >> 4) + 8 * j] = pa[j];
        }
#pragma unroll
        for (int j = 0; j < 5; ++j) *(float4*)(s_feat + 4 * t + 512 * j) = f4[j];
        __syncthreads();

        // ---- phase c: w[o][m] = mask * exp(lrelu(a_ope+a_mac)) ----
        // warp handles row o = 4*pass + warp; lanes cover m fully coalesced
#pragma unroll
        for (int pass = 0; pass < 10; ++pass) {
            int o = 4 * pass + warp;
            float so = s_aope[o];
            float4 p4 = __ldg((const float4*)(procB + (size_t)(ob + o) * Mn + lane * 4));
            float s0 = so + am4.x, s1 = so + am4.y, s2 = so + am4.z, s3 = so + am4.w;
            float4 w4;
            w4.x = (p4.x == 1.f) ? __expf(fmaxf(s0, 0.2f * s0)) : 0.f;
            w4.y = (p4.y == 1.f) ? __expf(fmaxf(s1, 0.2f * s1)) : 0.f;
            w4.z = (p4.z == 1.f) ? __expf(fmaxf(s2, 0.2f * s2)) : 0.f;
            w4.w = (p4.w == 1.f) ? __expf(fmaxf(s3, 0.2f * s3)) : 0.f;
            *(float4*)(s_w + o * 128 + lane * 4) = w4;
        }
        __syncthreads();

        // ---- phase b: register-tile accumulate (f32x2 FMA) ----
        const float* wbp = s_w + 8 * mg;
        const float* fbp = s_feat + 4 * dg;
#pragma unroll 2
        for (int o = 0; o < TO; ++o) {
            float4 wa = *(const float4*)(wbp + o * 128);
            float4 wb = *(const float4*)(wbp + o * 128 + 4);
            float4 fa = *(const float4*)(fbp + o * 64);
            float4 fb = *(const float4*)(fbp + o * 64 + 32);
            unsigned long long fp0 = pk2(fa.x, fa.y), fp1 = pk2(fa.z, fa.w);
            unsigned long long fp2 = pk2(fb.x, fb.y), fp3 = pk2(fb.z, fb.w);
            float wm[8] = {wa.x, wa.y, wa.z, wa.w, wb.x, wb.y, wb.z, wb.w};
#pragma unroll
            for (int mi = 0; mi < 8; ++mi) {
                unsigned long long wpk = pk2(wm[mi], wm[mi]);
                ffma2(acc[mi * 4 + 0], wpk, fp0);
                ffma2(acc[mi * 4 + 1], wpk, fp1);
                ffma2(acc[mi * 4 + 2], wpk, fp2);
                ffma2(acc[mi * 4 + 3], wpk, fp3);
            }
        }
        // Z partial: thread t owns m=t (conflict-free rows)
#pragma unroll
        for (int o = 0; o < TO; ++o) zacc += s_w[o * 128 + t];
        __syncthreads();
    }

    // ---- writeback split-K partials ----
    float* pbase = g_part + ((size_t)(b * SPLIT + sp) * Mn) * Dn;
#pragma unroll
    for (int mi = 0; mi < 8; ++mi) {
        int m = 8 * mg + mi;
#pragma unroll
        for (int pi = 0; pi < 4; ++pi) {
            int d0 = (pi < 2) ? (4 * dg + 2 * pi) : (32 + 4 * dg + 2 * (pi - 2));
            float2 v;
            upk2(acc[mi * 4 + pi], v.x, v.y);
            *(float2*)(pbase + (size_t)m * Dn + d0) = v;
        }
    }
    g_partZ[(b * SPLIT + sp) * Mn + t] = zacc;
}

// ---------------- kernel 4: combine partials, normalize, project, + h_mac -----
// grid (Bn, 2): half = 64 m's. 256 threads: k = t&63, mq = t>>6.
__global__ void finish_kernel(const float* __restrict__ W_ope, float* __restrict__ out) {
    const int b = blockIdx.x, half = blockIdx.y;
    const int t = threadIdx.x;
    const int mbase = 64 * half;
    const int k = t & 63, mq = t >> 6;

    __shared__ float s_inv[64];
    __shared__ float s_y[64 * 64];   // 16 KB

    // W_ope row k into registers (used in phase B)
    float4 Wr[16];
#pragma unroll
    for (int j = 0; j < 16; ++j)
        Wr[j] = __ldg((const float4*)(W_ope + (size_t)k * Dn + 4 * j));

    if (t < 64) {
        float z = 0.f;
#pragma unroll
        for (int s = 0; s < SPLIT; ++s) z += g_partZ[(b * SPLIT + s) * Mn + mbase + t];
        s_inv[t] = (z > 0.f) ? (1.f / z) : 0.f;
    }
    __syncthreads();

    // combine partial acc -> y = acc / Z
#pragma unroll
    for (int j = 0; j < 16; ++j) {
        int idx = t + 256 * j;
        int ml = idx >> 6, d = idx & 63;
        float a = 0.f;
#pragma unroll
        for (int s = 0; s < SPLIT; ++s)
            a += g_part[((size_t)(b * SPLIT + s) * Mn + mbase + ml) * Dn + d];
        s_y[idx] = a * s_inv[ml];
    }
    __syncthreads();

    // out[b, m, k] = sum_d y[m,d] * W_ope[k,d] + h_mac[b,m,k]
#pragma unroll
    for (int i = 0; i < 16; ++i) {
        int ml = mq * 16 + i;
        const float4* yr = (const float4*)(s_y + ml * 64);
        float a = 0.f;
#pragma unroll
        for (int j = 0; j < 16; ++j) {
            float4 y = yr[j];
            a += y.x * Wr[j].x + y.y * Wr[j].y + y.z * Wr[j].z + y.w * Wr[j].w;
        }
        size_t oidx = ((size_t)(b * Mn) + mbase + ml) * Dn + k;
        out[oidx] = a + g_hmac[oidx];
    }
}

// ---------------- launch --------------------------------------------------------
extern "C" void kernel_launch(void* const* d_in, const int* in_sizes, int n_in,
                              void* d_out, int out_size) {
    const float* proc      = (const float*)d_in[0];  // curr_proc_batch [B,O,M]
    // d_in[1] = batch_idxes (int64 arange) -- identity gather, ignored
    const float* feat_ope  = (const float*)d_in[2];  // [B,O,64]
    const float* feat_mac  = (const float*)d_in[3];  // [B,M,64]
    const float* W_ope     = (const float*)d_in[4];  // [64,64]
    const float* W_mac     = (const float*)d_in[5];  // [64,64]
    const float* alpha_ope = (const float*)d_in[6];  // [64]
    const float* alpha_mac = (const float*)d_in[7];  // [64]
    float* out = (float*)d_out;

    vope_kernel<<<1, 64>>>(W_ope, alpha_ope);
    hmac_kernel<<<Bn * Mn, 64>>>(feat_mac, W_mac, alpha_mac);
    main_kernel<<<dim3(SPLIT, Bn), 128>>>(proc, feat_ope);
    finish_kernel<<<dim3(Bn, 2), 256>>>(W_ope, out);
}

// round 4
// speedup vs baseline: 1.3088x; 1.3088x over previous
#include <cuda_runtime.h>

// Problem constants
#define Bn 64
#define On 4000
#define Mn 128
#define Dn 64
#define OS 9          // o-splits per batch -> grid = 64*9 = 576 CTAs
#define CHUNK0 448    // ope chunk for os<8 (448*8 + 416 = 4000)
#define TO 32         // opes per smem tile

// ---------------- device scratch ----------------------------------------------
__device__ float g_vope[Dn];
__device__ float g_amac[Bn * Mn];
__device__ float g_hmac[(size_t)Bn * Mn * Dn];
__device__ float g_part[(size_t)Bn * OS * Mn * Dn];      // 18.9 MB
__device__ float g_partZ[Bn * OS * 2 * Mn];

// ---------------- f32x2 helpers ------------------------------------------------
__device__ __forceinline__ unsigned long long pk2(float a, float b) {
    unsigned long long r;
    asm("mov.b64 %0, {%1,%2};" : "=l"(r) : "f"(a), "f"(b));
    return r;
}
__device__ __forceinline__ void upk2(unsigned long long v, float& a, float& b) {
    asm("mov.b64 {%0,%1}, %2;" : "=f"(a), "=f"(b) : "l"(v));
}
__device__ __forceinline__ void ffma2(unsigned long long& d, unsigned long long a,
                                      unsigned long long b) {
    asm("fma.rn.f32x2 %0, %1, %2, %0;" : "+l"(d) : "l"(a), "l"(b));
}

// ---------------- kernel 1: v = W_ope^T @ alpha_ope ---------------------------
__global__ void vope_kernel(const float* __restrict__ W_ope,
                            const float* __restrict__ alpha_ope) {
    int d = threadIdx.x;
    float s = 0.f;
#pragma unroll 8
    for (int k = 0; k < Dn; ++k) s += alpha_ope[k] * W_ope[k * Dn + d];
    g_vope[d] = s;
}

// ---------------- kernel 2: h_mac + a_mac -------------------------------------
__global__ void hmac_kernel(const float* __restrict__ feat_mac,
                            const float* __restrict__ W_mac,
                            const float* __restrict__ alpha_mac) {
    int bm = blockIdx.x;
    int k = threadIdx.x;
    const float4* fr = (const float4*)(feat_mac + (size_t)bm * Dn);
    const float4* wr = (const float4*)(W_mac + (size_t)k * Dn);
    float acc = 0.f;
#pragma unroll
    for (int j = 0; j < 16; ++j) {
        float4 f = __ldg(fr + j);
        float4 w = __ldg(wr + j);
        acc += f.x * w.x + f.y * w.y + f.z * w.z + f.w * w.w;
    }
    g_hmac[(size_t)bm * Dn + k] = acc;
    float pa = acc * __ldg(alpha_mac + k);
#pragma unroll
    for (int s = 16; s > 0; s >>= 1) pa += __shfl_xor_sync(0xFFFFFFFFu, pa, s);
    __shared__ float sred[2];
    if ((k & 31) == 0) sred[k >> 5] = pa;
    __syncthreads();
    if (k == 0) g_amac[bm] = sred[0] + sred[1];
}

// ---------------- kernel 3: main attention reduction --------------------------
// grid (OS, Bn), 256 threads. Full M=128 x D=64 accumulator per CTA.
// Thread tile: 8 m x 4 d -> 16 f32x2 accumulators.
//   mg = t>>4 (m = 8*mg..8*mg+7), dg = t&15 (d = 4*dg..4*dg+3)
__global__ void __launch_bounds__(256, 2)
main_kernel(const float* __restrict__ proc, const float* __restrict__ feat) {
    const int b = blockIdx.y, os = blockIdx.x;
    const int o0 = os * CHUNK0;
    const int o_cnt = (os == OS - 1) ? (On - (OS - 1) * CHUNK0) : CHUNK0;
    const int nt = o_cnt >> 5;   // 14 or 13 tiles of 32

    const int t = threadIdx.x, L = t & 31, wid = t >> 5;
    const int mg = t >> 4, dg = t & 15;
    const int m_z = t & 127, oh = (t >> 7) << 4;

    __shared__ float s_feat[2][TO * 64];   // 2 x 8 KB
    __shared__ float s_w[2][TO * 128];     // 2 x 16 KB  (total 48 KB)

    // per-thread constants
    float4 am4 = __ldg((const float4*)(g_amac + b * Mn + 4 * L));  // a_mac[m=4L..4L+3]
    float4 va = *(const float4*)(g_vope + (L & 7) * 8);
    float4 vb = *(const float4*)(g_vope + (L & 7) * 8 + 4);

    const float* featB = feat + (size_t)b * On * 64;
    const float* procB = proc + (size_t)b * On * 128;

    unsigned long long acc[16];
#pragma unroll
    for (int i = 0; i < 16; ++i) acc[i] = 0ull;
    float zacc = 0.f;

    // pipeline registers for next tile
    float4 fA, fB, p0, p1, p2, p3;

    // ---- prologue: load + stage tile 0 ----
    {
        const float* fp = featB + (size_t)(o0 + wid + 8 * (L >> 3)) * 64 + (L & 7) * 8;
        fA = __ldg((const float4*)fp);
        fB = __ldg((const float4*)(fp + 4));
        const float* pp = procB + (size_t)(o0 + wid) * 128 + 4 * L;
        p0 = __ldg((const float4*)pp);
        p1 = __ldg((const float4*)(pp + 8 * 128));
        p2 = __ldg((const float4*)(pp + 16 * 128));
        p3 = __ldg((const float4*)(pp + 24 * 128));
    }
    {
        float pa = fA.x * va.x + fA.y * va.y + fA.z * va.z + fA.w * va.w
                 + fB.x * vb.x + fB.y * vb.y + fB.z * vb.z + fB.w * vb.w;
        pa += __shfl_xor_sync(0xFFFFFFFFu, pa, 1);
        pa += __shfl_xor_sync(0xFFFFFFFFu, pa, 2);
        pa += __shfl_xor_sync(0xFFFFFFFFu, pa, 4);
        float* fd = &s_feat[0][(wid + 8 * (L >> 3)) * 64 + (L & 7) * 8];
        *(float4*)fd = fA;
        *(float4*)(fd + 4) = fB;
        float4 pr[4] = {p0, p1, p2, p3};
#pragma unroll
        for (int j = 0; j < 4; ++j) {
            float a = __shfl_sync(0xFFFFFFFFu, pa, 8 * j);
            float s0 = a + am4.x, s1 = a + am4.y, s2 = a + am4.z, s3 = a + am4.w;
            float4 w4;
            w4.x = (pr[j].x == 1.f) ? __expf(fmaxf(s0, 0.2f * s0)) : 0.f;
            w4.y = (pr[j].y == 1.f) ? __expf(fmaxf(s1, 0.2f * s1)) : 0.f;
            w4.z = (pr[j].z == 1.f) ? __expf(fmaxf(s2, 0.2f * s2)) : 0.f;
            w4.w = (pr[j].w == 1.f) ? __expf(fmaxf(s3, 0.2f * s3)) : 0.f;
            *(float4*)(&s_w[0][(wid + 8 * j) * 128 + 4 * L]) = w4;
        }
    }
    __syncthreads();

    for (int tile = 0; tile < nt; ++tile) {
        const int cur = tile & 1;
        const bool more = (tile + 1 < nt);
        if (more) {   // prefetch tile+1 into registers
            const int ob = o0 + (tile + 1) * TO;
            const float* fp = featB + (size_t)(ob + wid + 8 * (L >> 3)) * 64 + (L & 7) * 8;
            fA = __ldg((const float4*)fp);
            fB = __ldg((const float4*)(fp + 4));
            const float* pp = procB + (size_t)(ob + wid) * 128 + 4 * L;
            p0 = __ldg((const float4*)pp);
            p1 = __ldg((const float4*)(pp + 8 * 128));
            p2 = __ldg((const float4*)(pp + 16 * 128));
            p3 = __ldg((const float4*)(pp + 24 * 128));
        }

        // ---- FMA phase over current buffers ----
        const float* wbp = &s_w[cur][8 * mg];
        const float* fbp = &s_feat[cur][4 * dg];
#pragma unroll 4
        for (int o = 0; o < TO; ++o) {
            float4 wa = *(const float4*)(wbp + o * 128);
            float4 wb2 = *(const float4*)(wbp + o * 128 + 4);
            float4 fa = *(const float4*)(fbp + o * 64);
            unsigned long long f0 = pk2(fa.x, fa.y);
            unsigned long long f1 = pk2(fa.z, fa.w);
            float wm[8] = {wa.x, wa.y, wa.z, wa.w, wb2.x, wb2.y, wb2.z, wb2.w};
#pragma unroll
            for (int mi = 0; mi < 8; ++mi) {
                unsigned long long wpk = pk2(wm[mi], wm[mi]);
                ffma2(acc[2 * mi], wpk, f0);
                ffma2(acc[2 * mi + 1], wpk, f1);
            }
        }
        // ---- Z partial: thread owns (m_z, o-half) ----
#pragma unroll
        for (int oz = 0; oz < 16; ++oz) zacc += s_w[cur][(oh + oz) * 128 + m_z];

        if (more) {   // stage prefetched tile into other buffer
            const int nb = cur ^ 1;
            float pa = fA.x * va.x + fA.y * va.y + fA.z * va.z + fA.w * va.w
                     + fB.x * vb.x + fB.y * vb.y + fB.z * vb.z + fB.w * vb.w;
            pa += __shfl_xor_sync(0xFFFFFFFFu, pa, 1);
            pa += __shfl_xor_sync(0xFFFFFFFFu, pa, 2);
            pa += __shfl_xor_sync(0xFFFFFFFFu, pa, 4);
            float* fd = &s_feat[nb][(wid + 8 * (L >> 3)) * 64 + (L & 7) * 8];
            *(float4*)fd = fA;
            *(float4*)(fd + 4) = fB;
            float4 pr[4] = {p0, p1, p2, p3};
#pragma unroll
            for (int j = 0; j < 4; ++j) {
                float a = __shfl_sync(0xFFFFFFFFu, pa, 8 * j);
                float s0 = a + am4.x, s1 = a + am4.y, s2 = a + am4.z, s3 = a + am4.w;
                float4 w4;
                w4.x = (pr[j].x == 1.f) ? __expf(fmaxf(s0, 0.2f * s0)) : 0.f;
                w4.y = (pr[j].y == 1.f) ? __expf(fmaxf(s1, 0.2f * s1)) : 0.f;
                w4.z = (pr[j].z == 1.f) ? __expf(fmaxf(s2, 0.2f * s2)) : 0.f;
                w4.w = (pr[j].w == 1.f) ? __expf(fmaxf(s3, 0.2f * s3)) : 0.f;
                *(float4*)(&s_w[nb][(wid + 8 * j) * 128 + 4 * L]) = w4;
            }
        }
        __syncthreads();
    }

    // ---- writeback partials ----
    float* pbase = g_part + ((size_t)(b * OS + os) * Mn) * Dn;
#pragma unroll
    for (int mi = 0; mi < 8; ++mi) {
        int m = 8 * mg + mi;
        float2 v0, v1;
        upk2(acc[2 * mi], v0.x, v0.y);
        upk2(acc[2 * mi + 1], v1.x, v1.y);
        *(float2*)(pbase + (size_t)m * Dn + 4 * dg) = v0;
        *(float2*)(pbase + (size_t)m * Dn + 4 * dg + 2) = v1;
    }
    g_partZ[((b * OS + os) * 2 + (t >> 7)) * Mn + m_z] = zacc;
}

// ---------------- kernel 4: combine, normalize, project, + h_mac --------------
// grid (Bn, 4): 32-m strip per block. 256 threads.
__global__ void __launch_bounds__(256)
finish_kernel(const float* __restrict__ W_ope, float* __restrict__ out) {
    const int b = blockIdx.x, mq = blockIdx.y;
    const int mbase = 32 * mq;
    const int t = threadIdx.x;
    const int k = t & 63, mr = t >> 6;

    __shared__ float s_inv[32];
    __shared__ float s_y[32 * 64];   // 8 KB

    // Z
    if (t < 32) {
        float z = 0.f;
#pragma unroll
        for (int os = 0; os < OS; ++os) {
            z += g_partZ[((b * OS + os) * 2 + 0) * Mn + mbase + t];
            z += g_partZ[((b * OS + os) * 2 + 1) * Mn + mbase + t];
        }
        s_inv[t] = (z > 0.f) ? (1.f / z) : 0.f;
    }

    // combine partials (coalesced float4 streams)
    const int ml = t >> 3;            // 8 floats per thread: row ml, d = (8t)&63
    const int d0 = (8 * t) & 63;
    float4 a0 = {0, 0, 0, 0}, a1 = {0, 0, 0, 0};
#pragma unroll
    for (int os = 0; os < OS; ++os) {
        const float* pb = g_part + (((size_t)(b * OS + os) * Mn) + mbase + ml) * Dn + d0;
        float4 x0 = __ldg((const float4*)pb);
        float4 x1 = __ldg((const float4*)(pb + 4));
        a0.x += x0.x; a0.y += x0.y; a0.z += x0.z; a0.w += x0.w;
        a1.x += x1.x; a1.y += x1.y; a1.z += x1.z; a1.w += x1.w;
    }
    __syncthreads();
    {
        float inv = s_inv[ml];
        a0.x *= inv; a0.y *= inv; a0.z *= inv; a0.w *= inv;
        a1.x *= inv; a1.y *= inv; a1.z *= inv; a1.w *= inv;
        *(float4*)(s_y + ml * 64 + d0) = a0;
        *(float4*)(s_y + ml * 64 + d0 + 4) = a1;
    }
    __syncthreads();

    // project: out[b, m, k] = sum_d y[m,d] * W_ope[k,d] + h_mac
    float4 Wr[16];
#pragma unroll
    for (int j = 0; j < 16; ++j)
        Wr[j] = __ldg((const float4*)(W_ope + (size_t)k * Dn + 4 * j));

#pragma unroll
    for (int i = 0; i < 8; ++i) {
        int mloc = mr * 8 + i;
        const float4* yr = (const float4*)(s_y + mloc * 64);
        float a = 0.f;
#pragma unroll
        for (int j = 0; j < 16; ++j) {
            float4 y = yr[j];
            a += y.x * Wr[j].x + y.y * Wr[j].y + y.z * Wr[j].z + y.w * Wr[j].w;
        }
        size_t oidx = ((size_t)(b * Mn) + mbase + mloc) * Dn + k;
        out[oidx] = a + g_hmac[oidx];
    }
}

// ---------------- launch --------------------------------------------------------
extern "C" void kernel_launch(void* const* d_in, const int* in_sizes, int n_in,
                              void* d_out, int out_size) {
    const float* proc      = (const float*)d_in[0];
    const float* feat_ope  = (const float*)d_in[2];
    const float* feat_mac  = (const float*)d_in[3];
    const float* W_ope     = (const float*)d_in[4];
    const float* W_mac     = (const float*)d_in[5];
    const float* alpha_ope = (const float*)d_in[6];
    const float* alpha_mac = (const float*)d_in[7];
    float* out = (float*)d_out;

    vope_kernel<<<1, 64>>>(W_ope, alpha_ope);
    hmac_kernel<<<Bn * Mn, 64>>>(feat_mac, W_mac, alpha_mac);
    main_kernel<<<dim3(OS, Bn), 256>>>(proc, feat_ope);
    finish_kernel<<<dim3(Bn, 4), 256>>>(W_ope, out);
}

// round 5
// speedup vs baseline: 1.7130x; 1.3089x over previous
#include <cuda_runtime.h>
#include <cstdint>

// Problem constants
#define Bn 64
#define On 4000
#define Mn 128
#define Dn 64
#define OS 9          // o-splits per batch -> grid = 64*9 = 576 CTAs
#define CHUNK0 448    // ope chunk for os<8 (448*8 + 416 = 4000)
#define TO 32         // opes per smem tile

// ---------------- device scratch ----------------------------------------------
__device__ float g_vope[Dn];
__device__ float g_amac[Bn * Mn];
__device__ float g_hmac[(size_t)Bn * Mn * Dn];
__device__ float g_part[(size_t)Bn * OS * Mn * Dn];      // 18.9 MB
__device__ float g_partZ[Bn * OS * 2 * Mn];

// ---------------- helpers ------------------------------------------------------
__device__ __forceinline__ float to_tf32(float x) {
    uint32_t u;
    asm("cvt.rna.tf32.f32 %0, %1;" : "=r"(u) : "f"(x));
    return __uint_as_float(u);
}
__device__ __forceinline__ void mma_tf32(float* c, float a0, float a1, float a2, float a3,
                                         float b0, float b1) {
    asm volatile(
        "mma.sync.aligned.m16n8k8.row.col.f32.tf32.tf32.f32 "
        "{%0,%1,%2,%3}, {%4,%5,%6,%7}, {%8,%9}, {%0,%1,%2,%3};"
        : "+f"(c[0]), "+f"(c[1]), "+f"(c[2]), "+f"(c[3])
        : "r"(__float_as_uint(a0)), "r"(__float_as_uint(a1)),
          "r"(__float_as_uint(a2)), "r"(__float_as_uint(a3)),
          "r"(__float_as_uint(b0)), "r"(__float_as_uint(b1)));
}

// ---------------- kernel 1: h_mac + a_mac (+ vope in block 0) ------------------
__global__ void hmac_kernel(const float* __restrict__ feat_mac,
                            const float* __restrict__ W_mac,
                            const float* __restrict__ alpha_mac,
                            const float* __restrict__ W_ope,
                            const float* __restrict__ alpha_ope) {
    int bm = blockIdx.x;
    int k = threadIdx.x;
    const float4* fr = (const float4*)(feat_mac + (size_t)bm * Dn);
    const float4* wr = (const float4*)(W_mac + (size_t)k * Dn);
    float acc = 0.f;
#pragma unroll
    for (int j = 0; j < 16; ++j) {
        float4 f = __ldg(fr + j);
        float4 w = __ldg(wr + j);
        acc += f.x * w.x + f.y * w.y + f.z * w.z + f.w * w.w;
    }
    g_hmac[(size_t)bm * Dn + k] = acc;
    float pa = acc * __ldg(alpha_mac + k);
#pragma unroll
    for (int s = 16; s > 0; s >>= 1) pa += __shfl_xor_sync(0xFFFFFFFFu, pa, s);
    __shared__ float sred[2];
    if ((k & 31) == 0) sred[k >> 5] = pa;
    __syncthreads();
    if (k == 0) g_amac[bm] = sred[0] + sred[1];

    if (blockIdx.x == 0) {   // fused vope: g_vope = W_ope^T @ alpha_ope
        float s = 0.f;
#pragma unroll 8
        for (int kk = 0; kk < Dn; ++kk) s += alpha_ope[kk] * W_ope[kk * Dn + k];
        g_vope[k] = s;
    }
}

// ---------------- kernel 2: main attention reduction (tf32 mma) ----------------
// grid (OS, Bn), 256 threads (8 warps). C[128m x 64d] per CTA.
// Warp w owns m in [16w, 16w+16); 8 n-tiles (8 d each) -> 32 fp32 accums.
// smem tiles use XOR swizzle: col' = col ^ ((o&3)<<3)  (conflict-free frag loads)
__global__ void __launch_bounds__(256, 2)
main_kernel(const float* __restrict__ proc, const float* __restrict__ feat) {
    const int b = blockIdx.y, os = blockIdx.x;
    const int o0 = os * CHUNK0;
    const int o_cnt = (os == OS - 1) ? (On - (OS - 1) * CHUNK0) : CHUNK0;
    const int nt_tiles = o_cnt >> 5;   // 14 or 13 tiles of 32

    const int t = threadIdx.x, L = t & 31, wid = t >> 5;
    const int m_z = t & 127, oh = (t >> 7) << 4;
    const int r = L >> 2, kq = L & 3;        // fragment lane decomposition
    const int xa = kq << 3;                  // reader swizzle
    const int xw = (wid & 3) << 3;           // writer swizzle (rows o: o&3 == wid&3)

    __shared__ float s_feat[2][TO * 64];     // 2 x 8 KB
    __shared__ float s_w[2][TO * 128];       // 2 x 16 KB (total 48 KB)

    float4 am4 = __ldg((const float4*)(g_amac + b * Mn + 4 * L));
    float4 va = *(const float4*)(g_vope + (L & 7) * 8);
    float4 vb = *(const float4*)(g_vope + (L & 7) * 8 + 4);

    const float* featB = feat + (size_t)b * On * 64;
    const float* procB = proc + (size_t)b * On * 128;

    float cacc[8][4];
#pragma unroll
    for (int n = 0; n < 8; ++n)
#pragma unroll
        for (int i = 0; i < 4; ++i) cacc[n][i] = 0.f;
    float zacc = 0.f;

    float4 fA, fB, p0, p1, p2, p3;

    // ---- prologue: load + stage tile 0 ----
    {
        const float* fp = featB + (size_t)(o0 + wid + 8 * (L >> 3)) * 64 + (L & 7) * 8;
        fA = __ldg((const float4*)fp);
        fB = __ldg((const float4*)(fp + 4));
        const float* pp = procB + (size_t)(o0 + wid) * 128 + 4 * L;
        p0 = __ldg((const float4*)pp);
        p1 = __ldg((const float4*)(pp + 8 * 128));
        p2 = __ldg((const float4*)(pp + 16 * 128));
        p3 = __ldg((const float4*)(pp + 24 * 128));
    }
    {
        float pa = fA.x * va.x + fA.y * va.y + fA.z * va.z + fA.w * va.w
                 + fB.x * vb.x + fB.y * vb.y + fB.z * vb.z + fB.w * vb.w;
        pa += __shfl_xor_sync(0xFFFFFFFFu, pa, 1);
        pa += __shfl_xor_sync(0xFFFFFFFFu, pa, 2);
        pa += __shfl_xor_sync(0xFFFFFFFFu, pa, 4);
        float* fd = &s_feat[0][(wid + 8 * (L >> 3)) * 64 + (((L & 7) * 8) ^ xw)];
        float4 tA, tB;
        tA.x = to_tf32(fA.x); tA.y = to_tf32(fA.y); tA.z = to_tf32(fA.z); tA.w = to_tf32(fA.w);
        tB.x = to_tf32(fB.x); tB.y = to_tf32(fB.y); tB.z = to_tf32(fB.z); tB.w = to_tf32(fB.w);
        *(float4*)fd = tA;
        *(float4*)(fd + 4) = tB;
        float4 pr[4] = {p0, p1, p2, p3};
#pragma unroll
        for (int j = 0; j < 4; ++j) {
            float a = __shfl_sync(0xFFFFFFFFu, pa, 8 * j);
            float s0 = a + am4.x, s1 = a + am4.y, s2 = a + am4.z, s3 = a + am4.w;
            float4 w4;
            w4.x = (pr[j].x == 1.f) ? to_tf32(__expf(fmaxf(s0, 0.2f * s0))) : 0.f;
            w4.y = (pr[j].y == 1.f) ? to_tf32(__expf(fmaxf(s1, 0.2f * s1))) : 0.f;
            w4.z = (pr[j].z == 1.f) ? to_tf32(__expf(fmaxf(s2, 0.2f * s2))) : 0.f;
            w4.w = (pr[j].w == 1.f) ? to_tf32(__expf(fmaxf(s3, 0.2f * s3))) : 0.f;
            *(float4*)(&s_w[0][(wid + 8 * j) * 128 + ((4 * L) ^ xw)]) = w4;
        }
    }
    __syncthreads();

    for (int tile = 0; tile < nt_tiles; ++tile) {
        const int cur = tile & 1;
        const bool more = (tile + 1 < nt_tiles);
        if (more) {   // prefetch tile+1 into registers
            const int ob = o0 + (tile + 1) * TO;
            const float* fp = featB + (size_t)(ob + wid + 8 * (L >> 3)) * 64 + (L & 7) * 8;
            fA = __ldg((const float4*)fp);
            fB = __ldg((const float4*)(fp + 4));
            const float* pp = procB + (size_t)(ob + wid) * 128 + 4 * L;
            p0 = __ldg((const float4*)pp);
            p1 = __ldg((const float4*)(pp + 8 * 128));
            p2 = __ldg((const float4*)(pp + 16 * 128));
            p3 = __ldg((const float4*)(pp + 24 * 128));
        }

        // ---- MMA phase: C += w^T * feat over 32 opes ----
        {
            const float* sw = s_w[cur];
            const float* sf = s_feat[cur];
            const int m0 = 16 * wid;
            const int ca0 = (m0 + r) ^ xa;        // a-frag swizzled cols
            const int ca1 = (m0 + r + 8) ^ xa;
#pragma unroll
            for (int ks = 0; ks < 4; ++ks) {
                const int ro0 = (8 * ks + kq) * 128;
                const int ro1 = (8 * ks + kq + 4) * 128;
                float a0 = sw[ro0 + ca0];
                float a1 = sw[ro0 + ca1];
                float a2 = sw[ro1 + ca0];
                float a3 = sw[ro1 + ca1];
                const int fo0 = (8 * ks + kq) * 64;
                const int fo1 = (8 * ks + kq + 4) * 64;
#pragma unroll
                for (int n = 0; n < 8; ++n) {
                    const int cb = (8 * n + r) ^ xa;
                    float b0 = sf[fo0 + cb];
                    float b1 = sf[fo1 + cb];
                    mma_tf32(cacc[n], a0, a1, a2, a3, b0, b1);
                }
            }
        }
        // ---- Z partial: thread owns (m_z, o-half) ----
#pragma unroll
        for (int oz = 0; oz < 16; ++oz) {
            int o = oh + oz;
            zacc += s_w[cur][o * 128 + (m_z ^ ((o & 3) << 3))];
        }

        if (more) {   // stage prefetched tile into other buffer
            const int nb = cur ^ 1;
            float pa = fA.x * va.x + fA.y * va.y + fA.z * va.z + fA.w * va.w
                     + fB.x * vb.x + fB.y * vb.y + fB.z * vb.z + fB.w * vb.w;
            pa += __shfl_xor_sync(0xFFFFFFFFu, pa, 1);
            pa += __shfl_xor_sync(0xFFFFFFFFu, pa, 2);
            pa += __shfl_xor_sync(0xFFFFFFFFu, pa, 4);
            float* fd = &s_feat[nb][(wid + 8 * (L >> 3)) * 64 + (((L & 7) * 8) ^ xw)];
            float4 tA, tB;
            tA.x = to_tf32(fA.x); tA.y = to_tf32(fA.y); tA.z = to_tf32(fA.z); tA.w = to_tf32(fA.w);
            tB.x = to_tf32(fB.x); tB.y = to_tf32(fB.y); tB.z = to_tf32(fB.z); tB.w = to_tf32(fB.w);
            *(float4*)fd = tA;
            *(float4*)(fd + 4) = tB;
            float4 pr[4] = {p0, p1, p2, p3};
#pragma unroll
            for (int j = 0; j < 4; ++j) {
                float a = __shfl_sync(0xFFFFFFFFu, pa, 8 * j);
                float s0 = a + am4.x, s1 = a + am4.y, s2 = a + am4.z, s3 = a + am4.w;
                float4 w4;
                w4.x = (pr[j].x == 1.f) ? to_tf32(__expf(fmaxf(s0, 0.2f * s0))) : 0.f;
                w4.y = (pr[j].y == 1.f) ? to_tf32(__expf(fmaxf(s1, 0.2f * s1))) : 0.f;
                w4.z = (pr[j].z == 1.f) ? to_tf32(__expf(fmaxf(s2, 0.2f * s2))) : 0.f;
                w4.w = (pr[j].w == 1.f) ? to_tf32(__expf(fmaxf(s3, 0.2f * s3))) : 0.f;
                *(float4*)(&s_w[nb][(wid + 8 * j) * 128 + ((4 * L) ^ xw)]) = w4;
            }
        }
        __syncthreads();
    }

    // ---- writeback partials ----
    // c-reg (i, n): m = 16*wid + r (+8 for i>=2), d = 8n + 2*kq (+1 for odd i)
    float* pbase = g_part + ((size_t)(b * OS + os) * Mn) * Dn;
    const int mA = 16 * wid + r, mB = mA + 8;
#pragma unroll
    for (int n = 0; n < 8; ++n) {
        int d = 8 * n + 2 * kq;
        float2 v0 = {cacc[n][0], cacc[n][1]};
        float2 v1 = {cacc[n][2], cacc[n][3]};
        *(float2*)(pbase + (size_t)mA * Dn + d) = v0;
        *(float2*)(pbase + (size_t)mB * Dn + d) = v1;
    }
    g_partZ[((b * OS + os) * 2 + (t >> 7)) * Mn + m_z] = zacc;
}

// ---------------- kernel 3: combine, normalize, project, + h_mac --------------
// grid (Bn, 8): 16-m strip per block. 256 threads.
__global__ void __launch_bounds__(256)
finish_kernel(const float* __restrict__ W_ope, float* __restrict__ out) {
    const int b = blockIdx.x, mq = blockIdx.y;
    const int mbase = 16 * mq;
    const int t = threadIdx.x;
    const int k = t & 63, mr = t >> 6;

    __shared__ float s_inv[16];
    __shared__ float s_y[16 * 64];   // 4 KB

    if (t < 16) {
        float z = 0.f;
#pragma unroll
        for (int os = 0; os < OS; ++os) {
            z += g_partZ[((b * OS + os) * 2 + 0) * Mn + mbase + t];
            z += g_partZ[((b * OS + os) * 2 + 1) * Mn + mbase + t];
        }
        s_inv[t] = (z > 0.f) ? (1.f / z) : 0.f;
    }

    // combine partials: 16x64 floats, 1 float4 per thread
    const int ml = t >> 4;
    const int d0 = (t & 15) * 4;
    float4 a0 = {0, 0, 0, 0};
#pragma unroll
    for (int os = 0; os < OS; ++os) {
        const float* pb = g_part + (((size_t)(b * OS + os) * Mn) + mbase + ml) * Dn + d0;
        float4 x0 = __ldg((const float4*)pb);
        a0.x += x0.x; a0.y += x0.y; a0.z += x0.z; a0.w += x0.w;
    }
    __syncthreads();
    {
        float inv = s_inv[ml];
        a0.x *= inv; a0.y *= inv; a0.z *= inv; a0.w *= inv;
        *(float4*)(s_y + ml * 64 + d0) = a0;
    }
    __syncthreads();

    // project: out[b, m, k] = sum_d y[m,d] * W_ope[k,d] + h_mac
    float4 Wr[16];
#pragma unroll
    for (int j = 0; j < 16; ++j)
        Wr[j] = __ldg((const float4*)(W_ope + (size_t)k * Dn + 4 * j));

#pragma unroll
    for (int i = 0; i < 4; ++i) {
        int mloc = mr * 4 + i;
        const float4* yr = (const float4*)(s_y + mloc * 64);
        float a = 0.f;
#pragma unroll
        for (int j = 0; j < 16; ++j) {
            float4 y = yr[j];
            a += y.x * Wr[j].x + y.y * Wr[j].y + y.z * Wr[j].z + y.w * Wr[j].w;
        }
        size_t oidx = ((size_t)(b * Mn) + mbase + mloc) * Dn + k;
        out[oidx] = a + g_hmac[oidx];
    }
}

// ---------------- launch --------------------------------------------------------
extern "C" void kernel_launch(void* const* d_in, const int* in_sizes, int n_in,
                              void* d_out, int out_size) {
    const float* proc      = (const float*)d_in[0];
    const float* feat_ope  = (const float*)d_in[2];
    const float* feat_mac  = (const float*)d_in[3];
    const float* W_ope     = (const float*)d_in[4];
    const float* W_mac     = (const float*)d_in[5];
    const float* alpha_ope = (const float*)d_in[6];
    const float* alpha_mac = (const float*)d_in[7];
    float* out = (float*)d_out;

    hmac_kernel<<<Bn * Mn, 64>>>(feat_mac, W_mac, alpha_mac, W_ope, alpha_ope);
    main_kernel<<<dim3(OS, Bn), 256>>>(proc, feat_ope);
    finish_kernel<<<dim3(Bn, 8), 256>>>(W_ope, out);
}

// round 6
// speedup vs baseline: 2.2856x; 1.3343x over previous
#include <cuda_runtime.h>
#include <cstdint>

// Problem constants
#define Bn 64
#define On 4000
#define Mn 128
#define Dn 64
#define OS 9          // o-splits per batch -> grid = 64*9 = 576 CTAs
#define CHUNK0 448    // ope chunk for os<8 (448*8 + 416 = 4000)
#define TO 32         // opes per smem tile

// main-kernel dynamic smem: 3 stages x (proc 16KB + feat 8KB) = 72KB
#define STAGE_FLOATS 6144          // 24576 B / 4
#define FEAT_OFF     4096          // proc slot = 4096 floats, feat = 2048 floats
#define SMEM_MAIN    73728

// ---------------- device scratch ----------------------------------------------
__device__ float g_vope[Dn];
__device__ float g_vmac[Dn];
__device__ float g_amac[Bn * Mn];
__device__ float g_part[(size_t)Bn * OS * Mn * Dn];      // 18.9 MB
__device__ float g_partZ[Bn * OS * 2 * Mn];

// ---------------- helpers ------------------------------------------------------
__device__ __forceinline__ void mma_tf32(float* c, float a0, float a1, float a2, float a3,
                                         float b0, float b1) {
    asm volatile(
        "mma.sync.aligned.m16n8k8.row.col.f32.tf32.tf32.f32 "
        "{%0,%1,%2,%3}, {%4,%5,%6,%7}, {%8,%9}, {%0,%1,%2,%3};"
        : "+f"(c[0]), "+f"(c[1]), "+f"(c[2]), "+f"(c[3])
        : "r"(__float_as_uint(a0)), "r"(__float_as_uint(a1)),
          "r"(__float_as_uint(a2)), "r"(__float_as_uint(a3)),
          "r"(__float_as_uint(b0)), "r"(__float_as_uint(b1)));
}
__device__ __forceinline__ void cp16(uint32_t dst, const float* src) {
    asm volatile("cp.async.cg.shared.global [%0], [%1], 16;" :: "r"(dst), "l"(src));
}
__device__ __forceinline__ void cp_commit() {
    asm volatile("cp.async.commit_group;");
}
template <int N>
__device__ __forceinline__ void cp_wait() {
    asm volatile("cp.async.wait_group %0;" :: "n"(N));
}

// ---------------- kernel 0: v_ope, v_mac ---------------------------------------
__global__ void prep_kernel(const float* __restrict__ W_ope,
                            const float* __restrict__ alpha_ope,
                            const float* __restrict__ W_mac,
                            const float* __restrict__ alpha_mac) {
    int t = threadIdx.x;   // 128
    if (t < 64) {
        float s = 0.f;
#pragma unroll 8
        for (int k = 0; k < 64; ++k) s += alpha_ope[k] * W_ope[k * 64 + t];
        g_vope[t] = s;
    } else {
        int d = t - 64;
        float s = 0.f;
#pragma unroll 8
        for (int k = 0; k < 64; ++k) s += alpha_mac[k] * W_mac[k * 64 + d];
        g_vmac[d] = s;
    }
}

// ---------------- kernel 1: a_mac[b,m] = feat_mac[b,m,:] . v_mac ---------------
__global__ void amac_kernel(const float* __restrict__ feat_mac) {
    int b = blockIdx.x, t = threadIdx.x;   // 128 threads, thread = one m
    __shared__ float vs[64];
    if (t < 64) vs[t] = g_vmac[t];
    __syncthreads();
    const float4* fr = (const float4*)(feat_mac + ((size_t)b * Mn + t) * 64);
    float acc = 0.f;
#pragma unroll
    for (int j = 0; j < 16; ++j) {
        float4 f = __ldg(fr + j);
        acc += f.x * vs[4 * j] + f.y * vs[4 * j + 1] + f.z * vs[4 * j + 2] + f.w * vs[4 * j + 3];
    }
    g_amac[b * Mn + t] = acc;
}

// ---------------- kernel 2: main attention reduction (tf32 mma, cp.async) ------
// grid (OS, Bn), 256 threads (8 warps). C[128m x 64d] per CTA.
// 3-stage cp.async ring; w tile computed IN PLACE over the proc slot.
// feat ring chunk-swizzle: chunk' = chunk ^ ((row&3)<<1)   (16B chunks)
// w swizzle (float level): col' = col ^ ((o&3)<<3)
__global__ void __launch_bounds__(256, 3)
main_kernel(const float* __restrict__ proc, const float* __restrict__ feat) {
    extern __shared__ float smem[];
    const uint32_t sbase = (uint32_t)__cvta_generic_to_shared(smem);

    const int b = blockIdx.y, os = blockIdx.x;
    const int o0 = os * CHUNK0;
    const int o_cnt = (os == OS - 1) ? (On - (OS - 1) * CHUNK0) : CHUNK0;
    const int nt = o_cnt >> 5;   // 14 or 13 tiles of 32

    const int t = threadIdx.x, L = t & 31, wid = t >> 5;
    const int m_z = t & 127, oh = (t >> 7) << 4;
    const int r = L >> 2, kq = L & 3;
    const int xa = kq << 3;                  // a-frag swizzle
    const int xw = (wid & 3) << 3;           // w writer swizzle

    float4 am4 = __ldg((const float4*)(g_amac + b * Mn + 4 * L));
    float4 va = *(const float4*)(g_vope + (L & 7) * 8);
    float4 vb = *(const float4*)(g_vope + (L & 7) * 8 + 4);

    const float* featB = feat + (size_t)b * On * 64;
    const float* procB = proc + (size_t)b * On * 128;

    float cacc[8][4];
#pragma unroll
    for (int n = 0; n < 8; ++n)
#pragma unroll
        for (int i = 0; i < 4; ++i) cacc[n][i] = 0.f;
    float zacc = 0.f;

    // ---- issue cp.async for one tile into ring slot ----
    auto ISSUE = [&](int tile, int slot) {
        const int ob = o0 + tile * TO;
        const uint32_t pdst = sbase + slot * 24576;
        const uint32_t fdst = pdst + 16384;
        // proc: 1024 chunks, 4 per thread (contiguous 64B per thread -> coalesced)
#pragma unroll
        for (int i = 0; i < 4; ++i) {
            int c = 4 * t + i;
            cp16(pdst + c * 16, procB + (size_t)(ob + (c >> 5)) * 128 + (c & 31) * 4);
        }
        // feat: 512 chunks, 2 per thread, chunk-swizzled dst
#pragma unroll
        for (int i = 0; i < 2; ++i) {
            int c = 2 * t + i;
            int row = c >> 4, k = c & 15;
            int ks = k ^ ((row & 3) << 1);
            cp16(fdst + (row * 16 + ks) * 16, featB + (size_t)(ob + row) * 64 + k * 4);
        }
    };

    // ---- staging: compute a_ope + w (in place over proc slot) ----
    auto STAGE = [&](int slot) {
        float* Ps = smem + slot * STAGE_FLOATS;
        const float* Fs = Ps + FEAT_OFF;
        // a_ope for feat row R via octet reduction
        const int R = wid + 8 * (L >> 3);
        const int c0 = (2 * (L & 7)) ^ ((R & 3) << 1);     // even; c0+1 is its partner
        float4 fA = *(const float4*)(Fs + R * 64 + c0 * 4);
        float4 fB = *(const float4*)(Fs + R * 64 + (c0 + 1) * 4);
        float pa = fA.x * va.x + fA.y * va.y + fA.z * va.z + fA.w * va.w
                 + fB.x * vb.x + fB.y * vb.y + fB.z * vb.z + fB.w * vb.w;
        pa += __shfl_xor_sync(0xFFFFFFFFu, pa, 1);
        pa += __shfl_xor_sync(0xFFFFFFFFu, pa, 2);
        pa += __shfl_xor_sync(0xFFFFFFFFu, pa, 4);
        // read proc rows of this warp FIRST, then overwrite with w
        float4 p[4];
#pragma unroll
        for (int j = 0; j < 4; ++j)
            p[j] = *(const float4*)(Ps + (wid + 8 * j) * 128 + 4 * L);
        __syncwarp();
#pragma unroll
        for (int j = 0; j < 4; ++j) {
            float a = __shfl_sync(0xFFFFFFFFu, pa, 8 * j);
            float s0 = a + am4.x, s1 = a + am4.y, s2 = a + am4.z, s3 = a + am4.w;
            float4 w4;
            w4.x = (p[j].x == 1.f) ? __expf(fmaxf(s0, 0.2f * s0)) : 0.f;
            w4.y = (p[j].y == 1.f) ? __expf(fmaxf(s1, 0.2f * s1)) : 0.f;
            w4.z = (p[j].z == 1.f) ? __expf(fmaxf(s2, 0.2f * s2)) : 0.f;
            w4.w = (p[j].w == 1.f) ? __expf(fmaxf(s3, 0.2f * s3)) : 0.f;
            *(float4*)(Ps + (wid + 8 * j) * 128 + ((4 * L) ^ xw)) = w4;
        }
    };

    // ---- prologue ----
    ISSUE(0, 0); cp_commit();
    if (nt > 1) ISSUE(1, 1);
    cp_commit();
    cp_wait<1>();
    __syncthreads();
    STAGE(0);
    __syncthreads();

    for (int tl = 0; tl < nt; ++tl) {
        const int slot = tl % 3;
        if (tl + 2 < nt) ISSUE(tl + 2, (tl + 2) % 3);
        cp_commit();

        // ---- MMA phase: C += w^T * feat over 32 opes ----
        {
            const float* Ws = smem + slot * STAGE_FLOATS;
            const float* Fs = Ws + FEAT_OFF;
            const int m0 = 16 * wid;
            const int ca0 = (m0 + r) ^ xa;
            const int ca1 = (m0 + r + 8) ^ xa;
#pragma unroll
            for (int ks = 0; ks < 4; ++ks) {
                const int ro0 = (8 * ks + kq) * 128;
                const int ro1 = (8 * ks + kq + 4) * 128;
                float a0 = Ws[ro0 + ca0];
                float a1 = Ws[ro0 + ca1];
                float a2 = Ws[ro1 + ca0];
                float a3 = Ws[ro1 + ca1];
                const int fr0 = (8 * ks + kq) * 64;
                const int fr1 = (8 * ks + kq + 4) * 64;
#pragma unroll
                for (int n = 0; n < 8; ++n) {
                    const int cb = ((2 * n + (r >> 2)) ^ (kq << 1)) * 4 + (r & 3);
                    float b0 = Fs[fr0 + cb];
                    float b1 = Fs[fr1 + cb];
                    mma_tf32(cacc[n], a0, a1, a2, a3, b0, b1);
                }
            }
            // Z partial
#pragma unroll
            for (int oz = 0; oz < 16; ++oz) {
                int o = oh + oz;
                zacc += Ws[o * 128 + (m_z ^ ((o & 3) << 3))];
            }
        }

        if (tl + 1 < nt) {
            cp_wait<1>();        // tile tl+1 resident (tl+2 may still fly)
            __syncthreads();     // all threads' copies visible; w[slot] consumed
            STAGE((tl + 1) % 3);
        }
        __syncthreads();
    }

    // ---- writeback partials ----
    float* pbase = g_part + ((size_t)(b * OS + os) * Mn) * Dn;
    const int mA = 16 * wid + r, mB = mA + 8;
#pragma unroll
    for (int n = 0; n < 8; ++n) {
        int d = 8 * n + 2 * kq;
        float2 v0 = {cacc[n][0], cacc[n][1]};
        float2 v1 = {cacc[n][2], cacc[n][3]};
        *(float2*)(pbase + (size_t)mA * Dn + d) = v0;
        *(float2*)(pbase + (size_t)mB * Dn + d) = v1;
    }
    g_partZ[((b * OS + os) * 2 + (t >> 7)) * Mn + m_z] = zacc;
}

// ---------------- kernel 3: combine + normalize + project + fused h_mac --------
// grid (Bn, 8): 16-m strip per block. 256 threads.
// out[b,m,k] = (sum_part/Z) . W_ope[k,:] + feat_mac[b,m,:] . W_mac[k,:]
__global__ void __launch_bounds__(256)
finish_kernel(const float* __restrict__ W_ope, const float* __restrict__ W_mac,
              const float* __restrict__ feat_mac, float* __restrict__ out) {
    const int b = blockIdx.x, mq = blockIdx.y;
    const int mbase = 16 * mq;
    const int t = threadIdx.x;
    const int k = t & 63, mr = t >> 6;

    __shared__ float s_inv[16];
    __shared__ float s_y[16 * 64];       // 4 KB
    __shared__ float s_fm[16 * 64];      // 4 KB
    __shared__ float s_W[64 * 68];       // 17 KB (pitch 68 -> conflict-free)
    __shared__ float s_Wm[64 * 68];      // 17 KB

    // load W_ope / W_mac padded (4 float4 rows-chunks per thread, coalesced)
#pragma unroll
    for (int qq = 0; qq < 4; ++qq) {
        int q = t + 256 * qq;            // 0..1023 float4 units
        int kk = q >> 4, j = q & 15;
        *(float4*)(s_W + kk * 68 + 4 * j) = __ldg((const float4*)(W_ope + kk * 64 + 4 * j));
        *(float4*)(s_Wm + kk * 68 + 4 * j) = __ldg((const float4*)(W_mac + kk * 64 + 4 * j));
    }
    // load feat_mac strip (1 float4 per thread, coalesced)
    {
        int row = t >> 4, c = 4 * (t & 15);
        *(float4*)(s_fm + row * 64 + c) =
            __ldg((const float4*)(feat_mac + ((size_t)b * Mn + mbase + row) * 64 + c));
    }
    if (t < 16) {
        float z = 0.f;
#pragma unroll
        for (int os = 0; os < OS; ++os) {
            z += g_partZ[((b * OS + os) * 2 + 0) * Mn + mbase + t];
            z += g_partZ[((b * OS + os) * 2 + 1) * Mn + mbase + t];
        }
        s_inv[t] = (z > 0.f) ? (1.f / z) : 0.f;
    }

    // combine partials: 16x64 floats, 1 float4 per thread
    const int ml = t >> 4;
    const int d0 = (t & 15) * 4;
    float4 a0 = {0, 0, 0, 0};
#pragma unroll
    for (int os = 0; os < OS; ++os) {
        const float* pb = g_part + (((size_t)(b * OS + os) * Mn) + mbase + ml) * Dn + d0;
        float4 x0 = __ldg((const float4*)pb);
        a0.x += x0.x; a0.y += x0.y; a0.z += x0.z; a0.w += x0.w;
    }
    __syncthreads();
    {
        float inv = s_inv[ml];
        a0.x *= inv; a0.y *= inv; a0.z *= inv; a0.w *= inv;
        *(float4*)(s_y + ml * 64 + d0) = a0;
    }
    __syncthreads();

    // project both terms
    float accv[4] = {0.f, 0.f, 0.f, 0.f};
#pragma unroll
    for (int j = 0; j < 16; ++j) {
        float4 wr = *(const float4*)(s_W + k * 68 + 4 * j);
        float4 wm = *(const float4*)(s_Wm + k * 68 + 4 * j);
#pragma unroll
        for (int i = 0; i < 4; ++i) {
            int mloc = mr * 4 + i;
            float4 y = *(const float4*)(s_y + mloc * 64 + 4 * j);
            float4 fm = *(const float4*)(s_fm + mloc * 64 + 4 * j);
            accv[i] += y.x * wr.x + y.y * wr.y + y.z * wr.z + y.w * wr.w
                     + fm.x * wm.x + fm.y * wm.y + fm.z * wm.z + fm.w * wm.w;
        }
    }
#pragma unroll
    for (int i = 0; i < 4; ++i) {
        int mloc = mr * 4 + i;
        out[((size_t)(b * Mn) + mbase + mloc) * Dn + k] = accv[i];
    }
}

// ---------------- launch --------------------------------------------------------
extern "C" void kernel_launch(void* const* d_in, const int* in_sizes, int n_in,
                              void* d_out, int out_size) {
    const float* proc      = (const float*)d_in[0];
    const float* feat_ope  = (const float*)d_in[2];
    const float* feat_mac  = (const float*)d_in[3];
    const float* W_ope     = (const float*)d_in[4];
    const float* W_mac     = (const float*)d_in[5];
    const float* alpha_ope = (const float*)d_in[6];
    const float* alpha_mac = (const float*)d_in[7];
    float* out = (float*)d_out;

    static int smem_set = 0;
    if (!smem_set) {
        cudaFuncSetAttribute(main_kernel, cudaFuncAttributeMaxDynamicSharedMemorySize,
                             SMEM_MAIN);
        smem_set = 1;
    }

    prep_kernel<<<1, 128>>>(W_ope, alpha_ope, W_mac, alpha_mac);
    amac_kernel<<<Bn, 128>>>(feat_mac);
    main_kernel<<<dim3(OS, Bn), 256, SMEM_MAIN>>>(proc, feat_ope);
    finish_kernel<<<dim3(Bn, 8), 256>>>(W_ope, W_mac, feat_mac, out);
}

// round 8
// speedup vs baseline: 2.5140x; 1.0999x over previous
#include <cuda_runtime.h>
#include <cstdint>

// Problem constants
#define Bn 64
#define On 4000
#define Mn 128
#define Dn 64
#define TO 32           // opes per tile
#define TPB 125         // tiles per batch (4000/32)
#define G_TILES 8000    // total tiles (64*125)
#define NC 444          // CTAs = 3 per SM x 148 SMs, single wave

// main-kernel dynamic smem: 3 stages x (proc 16KB + feat 8KB) = 72KB
#define STAGE_FLOATS 6144
#define FEAT_OFF     4096
#define SMEM_MAIN    73728

// finish smem: W 4352 + Wm 4352 + y 2048 + fm 2048 + inv 32 floats
#define FIN_SMEM     (12832 * 4)

// ---------------- device scratch ----------------------------------------------
__device__ float g_vope[Dn];
__device__ float g_vmac[Dn];
__device__ float g_amac[Bn * Mn];
__device__ float g_part[(size_t)NC * 2 * Mn * Dn];   // 27.7 MB
__device__ float g_partZ[NC * 2 * Mn];

// ---------------- helpers ------------------------------------------------------
__device__ __forceinline__ void mma_tf32(float* c, float a0, float a1, float a2, float a3,
                                         float b0, float b1) {
    asm volatile(
        "mma.sync.aligned.m16n8k8.row.col.f32.tf32.tf32.f32 "
        "{%0,%1,%2,%3}, {%4,%5,%6,%7}, {%8,%9}, {%0,%1,%2,%3};"
        : "+f"(c[0]), "+f"(c[1]), "+f"(c[2]), "+f"(c[3])
        : "r"(__float_as_uint(a0)), "r"(__float_as_uint(a1)),
          "r"(__float_as_uint(a2)), "r"(__float_as_uint(a3)),
          "r"(__float_as_uint(b0)), "r"(__float_as_uint(b1)));
}
__device__ __forceinline__ void cp16(uint32_t dst, const float* src) {
    asm volatile("cp.async.cg.shared.global [%0], [%1], 16;" :: "r"(dst), "l"(src));
}
__device__ __forceinline__ void cp_commit() {
    asm volatile("cp.async.commit_group;");
}
template <int N>
__device__ __forceinline__ void cp_wait() {
    asm volatile("cp.async.wait_group %0;" :: "n"(N));
}

// ---------------- kernel 0: v_ope, v_mac ---------------------------------------
__global__ void prep_kernel(const float* __restrict__ W_ope,
                            const float* __restrict__ alpha_ope,
                            const float* __restrict__ W_mac,
                            const float* __restrict__ alpha_mac) {
    int t = threadIdx.x;   // 128
    if (t < 64) {
        float s = 0.f;
#pragma unroll 8
        for (int k = 0; k < 64; ++k) s += alpha_ope[k] * W_ope[k * 64 + t];
        g_vope[t] = s;
    } else {
        int d = t - 64;
        float s = 0.f;
#pragma unroll 8
        for (int k = 0; k < 64; ++k) s += alpha_mac[k] * W_mac[k * 64 + d];
        g_vmac[d] = s;
    }
}

// ---------------- kernel 1: a_mac ----------------------------------------------
__global__ void amac_kernel(const float* __restrict__ feat_mac) {
    int b = blockIdx.x, t = threadIdx.x;   // 128 threads, thread = one m
    __shared__ float vs[64];
    if (t < 64) vs[t] = g_vmac[t];
    __syncthreads();
    const float4* fr = (const float4*)(feat_mac + ((size_t)b * Mn + t) * 64);
    float acc = 0.f;
#pragma unroll
    for (int j = 0; j < 16; ++j) {
        float4 f = __ldg(fr + j);
        acc += f.x * vs[4 * j] + f.y * vs[4 * j + 1] + f.z * vs[4 * j + 2] + f.w * vs[4 * j + 3];
    }
    g_amac[b * Mn + t] = acc;
}

// ---------------- kernel 2: main (flat balanced grid, tf32 mma) -----------------
// 444 CTAs x 256 threads. CTA i owns global tiles [i*8000/444, (i+1)*8000/444).
// cp.async 3-slot ring (proc+feat), w computed in place over proc slot.
// Z accumulated via a 9th MMA n-tile with B == 1.
__global__ void __launch_bounds__(256, 3)
main_kernel(const float* __restrict__ proc, const float* __restrict__ feat) {
    extern __shared__ float smem[];
    const uint32_t sbase = (uint32_t)__cvta_generic_to_shared(smem);

    const int cta = blockIdx.x;
    const int g0 = (cta * G_TILES) / NC;
    const int g1 = ((cta + 1) * G_TILES) / NC;
    const int n = g1 - g0;

    const int t = threadIdx.x, L = t & 31, wid = t >> 5;
    const int r = L >> 2, kq = L & 3;
    const int xa = kq << 3;                  // a-frag swizzle
    const int xw = (wid & 3) << 3;           // w writer swizzle

    float4 va = *(const float4*)(g_vope + (L & 7) * 8);
    float4 vb = *(const float4*)(g_vope + (L & 7) * 8 + 4);

    float cacc[9][4];
#pragma unroll
    for (int nn = 0; nn < 9; ++nn)
#pragma unroll
        for (int i = 0; i < 4; ++i) cacc[nn][i] = 0.f;

    // ---- issue cp.async for tile g into its ring slot ----
    auto ISSUE = [&](int g) {
        if (g >= g1) return;
        const int bb = g / TPB;
        const int ob = (g % TPB) * TO;
        const float* procB = proc + ((size_t)bb * On + ob) * 128;
        const float* featB = feat + ((size_t)bb * On + ob) * 64;
        const int slot = (g - g0) % 3;
        const uint32_t pdst = sbase + (uint32_t)slot * 24576u;
        const uint32_t fdst = pdst + 16384u;
#pragma unroll
        for (int i = 0; i < 4; ++i) {
            int c = 4 * t + i;
            cp16(pdst + c * 16, procB + (size_t)(c >> 5) * 128 + (c & 31) * 4);
        }
#pragma unroll
        for (int i = 0; i < 2; ++i) {
            int c = 2 * t + i;
            int row = c >> 4, k = c & 15;
            int ks2 = k ^ ((row & 3) << 1);
            cp16(fdst + (row * 16 + ks2) * 16, featB + (size_t)row * 64 + k * 4);
        }
    };

    // ---- stage: a_ope + w in place over proc slot ----
    auto STAGE = [&](int g) {
        const int slot = (g - g0) % 3;
        const int bb = g / TPB;
        float4 am4 = __ldg((const float4*)(g_amac + bb * Mn + 4 * L));
        float* Ps = smem + slot * STAGE_FLOATS;
        const float* Fs = Ps + FEAT_OFF;
        const int R = wid + 8 * (L >> 3);
        const int c0 = (2 * (L & 7)) ^ ((R & 3) << 1);
        float4 fA = *(const float4*)(Fs + R * 64 + c0 * 4);
        float4 fB = *(const float4*)(Fs + R * 64 + (c0 + 1) * 4);
        float pa = fA.x * va.x + fA.y * va.y + fA.z * va.z + fA.w * va.w
                 + fB.x * vb.x + fB.y * vb.y + fB.z * vb.z + fB.w * vb.w;
        pa += __shfl_xor_sync(0xFFFFFFFFu, pa, 1);
        pa += __shfl_xor_sync(0xFFFFFFFFu, pa, 2);
        pa += __shfl_xor_sync(0xFFFFFFFFu, pa, 4);
        float4 p[4];
#pragma unroll
        for (int j = 0; j < 4; ++j)
            p[j] = *(const float4*)(Ps + (wid + 8 * j) * 128 + 4 * L);
        __syncwarp();
#pragma unroll
        for (int j = 0; j < 4; ++j) {
            float a = __shfl_sync(0xFFFFFFFFu, pa, 8 * j);
            float s0 = a + am4.x, s1 = a + am4.y, s2 = a + am4.z, s3 = a + am4.w;
            float4 w4;
            w4.x = (p[j].x == 1.f) ? __expf(fmaxf(s0, 0.2f * s0)) : 0.f;
            w4.y = (p[j].y == 1.f) ? __expf(fmaxf(s1, 0.2f * s1)) : 0.f;
            w4.z = (p[j].z == 1.f) ? __expf(fmaxf(s2, 0.2f * s2)) : 0.f;
            w4.w = (p[j].w == 1.f) ? __expf(fmaxf(s3, 0.2f * s3)) : 0.f;
            *(float4*)(Ps + (wid + 8 * j) * 128 + ((4 * L) ^ xw)) = w4;
        }
    };

    // ---- MMA over one staged tile ----
    auto MMAF = [&](int slot) {
        const float* Ws = smem + slot * STAGE_FLOATS;
        const float* Fs = Ws + FEAT_OFF;
        const int m0 = 16 * wid;
        const int ca0 = (m0 + r) ^ xa;
        const int ca1 = (m0 + r + 8) ^ xa;
#pragma unroll
        for (int ks = 0; ks < 4; ++ks) {
            const int ro0 = (8 * ks + kq) * 128;
            const int ro1 = (8 * ks + kq + 4) * 128;
            float a0 = Ws[ro0 + ca0];
            float a1 = Ws[ro0 + ca1];
            float a2 = Ws[ro1 + ca0];
            float a3 = Ws[ro1 + ca1];
            const int fr0 = (8 * ks + kq) * 64;
            const int fr1 = (8 * ks + kq + 4) * 64;
#pragma unroll
            for (int nn = 0; nn < 8; ++nn) {
                const int cb = ((2 * nn + (r >> 2)) ^ (kq << 1)) * 4 + (r & 3);
                mma_tf32(cacc[nn], a0, a1, a2, a3, Fs[fr0 + cb], Fs[fr1 + cb]);
            }
            mma_tf32(cacc[8], a0, a1, a2, a3, 1.0f, 1.0f);   // Z tile (B == 1)
        }
    };

    // ---- flush accumulator segment ----
    auto FLUSH = [&](int seg) {
        float* pbase = g_part + ((size_t)(cta * 2 + seg) * Mn) * Dn;
        const int mA = 16 * wid + r, mB = mA + 8;
#pragma unroll
        for (int nn = 0; nn < 8; ++nn) {
            int d = 8 * nn + 2 * kq;
            float2 v0 = {cacc[nn][0], cacc[nn][1]};
            float2 v1 = {cacc[nn][2], cacc[nn][3]};
            *(float2*)(pbase + (size_t)mA * Dn + d) = v0;
            *(float2*)(pbase + (size_t)mB * Dn + d) = v1;
        }
        if (kq == 0) {
            g_partZ[(cta * 2 + seg) * Mn + mA] = cacc[8][0];
            g_partZ[(cta * 2 + seg) * Mn + mB] = cacc[8][2];
        }
#pragma unroll
        for (int nn = 0; nn < 9; ++nn)
#pragma unroll
            for (int i = 0; i < 4; ++i) cacc[nn][i] = 0.f;
    };

    // ---- prologue ----
    ISSUE(g0); cp_commit();
    ISSUE(g0 + 1); cp_commit();
    cp_wait<1>();
    __syncthreads();
    STAGE(g0);
    __syncthreads();

    int seg = 0;
    for (int lt = 0; lt < n; ++lt) {
        const int g = g0 + lt;
        ISSUE(g + 2); cp_commit();
        cp_wait<1>();
        __syncthreads();                 // tile g+1 copies visible to all
        if (lt + 1 < n) STAGE(g + 1);    // overlaps with MMA across warps
        MMAF(lt % 3);
        if (lt + 1 == n || (g + 1) % TPB == 0) { FLUSH(seg); ++seg; }
        __syncthreads();                 // staged w(g+1) visible; slot reuse safe
    }
}

// ---------------- kernel 3: combine + normalize + project + fused h_mac --------
// grid (Bn, 4): 32-m strip per block, 256 threads.
__global__ void __launch_bounds__(256)
finish_kernel(const float* __restrict__ W_ope, const float* __restrict__ W_mac,
              const float* __restrict__ feat_mac, float* __restrict__ out) {
    extern __shared__ float fs[];
    float* s_W   = fs;                   // 64 x 68
    float* s_Wm  = fs + 4352;            // 64 x 68
    float* s_y   = fs + 8704;            // 32 x 64
    float* s_fm  = fs + 8704 + 2048;     // 32 x 64
    float* s_inv = fs + 8704 + 4096;     // 32

    const int b = blockIdx.x, mq = blockIdx.y;
    const int mbase = 32 * mq;
    const int t = threadIdx.x;
    const int k = t & 63, mr = t >> 6;

    // load W_ope / W_mac padded
#pragma unroll
    for (int qq = 0; qq < 4; ++qq) {
        int q = t + 256 * qq;
        int kk = q >> 4, j = q & 15;
        *(float4*)(s_W + kk * 68 + 4 * j) = __ldg((const float4*)(W_ope + kk * 64 + 4 * j));
        *(float4*)(s_Wm + kk * 68 + 4 * j) = __ldg((const float4*)(W_mac + kk * 64 + 4 * j));
    }
    // feat_mac strip
#pragma unroll
    for (int i = 0; i < 2; ++i) {
        int q = t + 256 * i;
        int row = q >> 4, c = 4 * (q & 15);
        *(float4*)(s_fm + row * 64 + c) =
            __ldg((const float4*)(feat_mac + ((size_t)b * Mn + mbase + row) * 64 + c));
    }

    // candidate partial slots for this batch (static map)
    const int i_lo = (int)(((long long)(TPB * b)) * NC / G_TILES);
    const int i_hi = (int)(((long long)(TPB * (b + 1) - 1)) * NC / G_TILES);

    const int ml = t >> 3;            // 8 floats/thread: row ml, d = (t&7)*8
    const int d0 = (t & 7) * 8;
    float4 a0 = {0, 0, 0, 0}, a1 = {0, 0, 0, 0};
    float z = 0.f;
    for (int i = i_lo; i <= i_hi; ++i) {
        int gi0 = (i * G_TILES) / NC, gi1 = ((i + 1) * G_TILES) / NC;
        int b0i = gi0 / TPB, b1i = (gi1 - 1) / TPB;
        int sg;
        if (b == b0i) sg = 0;
        else if (b == b1i) sg = 1;
        else continue;
        const float* pb = g_part + ((size_t)(i * 2 + sg) * Mn + mbase + ml) * Dn + d0;
        float4 x0 = __ldg((const float4*)pb);
        float4 x1 = __ldg((const float4*)(pb + 4));
        a0.x += x0.x; a0.y += x0.y; a0.z += x0.z; a0.w += x0.w;
        a1.x += x1.x; a1.y += x1.y; a1.z += x1.z; a1.w += x1.w;
        if (t < 32) z += g_partZ[(i * 2 + sg) * Mn + mbase + t];
    }
    if (t < 32) s_inv[t] = (z > 0.f) ? (1.f / z) : 0.f;
    __syncthreads();
    {
        float inv = s_inv[ml];
        a0.x *= inv; a0.y *= inv; a0.z *= inv; a0.w *= inv;
        a1.x *= inv; a1.y *= inv; a1.z *= inv; a1.w *= inv;
        *(float4*)(s_y + ml * 64 + d0) = a0;
        *(float4*)(s_y + ml * 64 + d0 + 4) = a1;
    }
    __syncthreads();

    // project both terms: out = y.W_ope^T + feat_mac.W_mac^T
    float accv[8] = {0.f, 0.f, 0.f, 0.f, 0.f, 0.f, 0.f, 0.f};
#pragma unroll
    for (int j = 0; j < 16; ++j) {
        float4 wr = *(const float4*)(s_W + k * 68 + 4 * j);
        float4 wm = *(const float4*)(s_Wm + k * 68 + 4 * j);
#pragma unroll
        for (int i = 0; i < 8; ++i) {
            int mloc = mr * 8 + i;
            float4 y = *(const float4*)(s_y + mloc * 64 + 4 * j);
            float4 fm = *(const float4*)(s_fm + mloc * 64 + 4 * j);
            accv[i] += y.x * wr.x + y.y * wr.y + y.z * wr.z + y.w * wr.w
                     + fm.x * wm.x + fm.y * wm.y + fm.z * wm.z + fm.w * wm.w;
        }
    }
#pragma unroll
    for (int i = 0; i < 8; ++i)
        out[((size_t)(b * Mn) + mbase + mr * 8 + i) * Dn + k] = accv[i];
}

// ---------------- launch --------------------------------------------------------
extern "C" void kernel_launch(void* const* d_in, const int* in_sizes, int n_in,
                              void* d_out, int out_size) {
    const float* proc      = (const float*)d_in[0];
    const float* feat_ope  = (const float*)d_in[2];
    const float* feat_mac  = (const float*)d_in[3];
    const float* W_ope     = (const float*)d_in[4];
    const float* W_mac     = (const float*)d_in[5];
    const float* alpha_ope = (const float*)d_in[6];
    const float* alpha_mac = (const float*)d_in[7];
    float* out = (float*)d_out;

    static int smem_set = 0;
    if (!smem_set) {
        cudaFuncSetAttribute(main_kernel, cudaFuncAttributeMaxDynamicSharedMemorySize,
                             SMEM_MAIN);
        cudaFuncSetAttribute(finish_kernel, cudaFuncAttributeMaxDynamicSharedMemorySize,
                             FIN_SMEM);
        smem_set = 1;
    }

    prep_kernel<<<1, 128>>>(W_ope, alpha_ope, W_mac, alpha_mac);
    amac_kernel<<<Bn, 128>>>(feat_mac);
    main_kernel<<<NC, 256, SMEM_MAIN>>>(proc, feat_ope);
    finish_kernel<<<dim3(Bn, 4), 256, FIN_SMEM>>>(W_ope, W_mac, feat_mac, out);
}